// round 16
// baseline (speedup 1.0000x reference)
#include <cuda_runtime.h>
#include <cuda.h>
#include <cuda_fp16.h>
#include <stdint.h>
#include <math.h>

#define T_TOK 1024
#define H_DIM 2048
#define F_DIM 4096
#define E_EXP 8
#define ROWS_CAP 3072
#define MTILES (ROWS_CAP / 128)   // 24
#define KSPLIT 4
#define NCTA 296                  // 148 SMs x 2 CTAs
#define NT13 (64 * MTILES)        // 1536 tiles (bn x my)
#define NT2 (16 * MTILES * KSPLIT)

// stage = A(16KB fp16 SW128) + B panels (f32 SW128, 8KB each)
#define STG13_B 49152u
#define SMEM13 (1024 + 64 + 2 * 49152)
#define STG2_B 49152u
#define SMEM2 (1024 + 64 + 2 * 49152)

// ---------------- scratch ----------------
__device__ __align__(256) __half g_X[(size_t)ROWS_CAP * H_DIM];
__device__ __align__(256) __half g_A[(size_t)ROWS_CAP * F_DIM];
__device__ __align__(256) float  g_Y[(size_t)KSPLIT * ROWS_CAP * H_DIM];
__device__ int   g_off[E_EXP + 1];
__device__ int   g_tile_e[MTILES];
__device__ int   g_rows[ROWS_CAP];
__device__ float g_rw[ROWS_CAP];
__device__ int   g_pos[T_TOK * 2];
__device__ int   g_te[T_TOK * 2];
__device__ float g_tw[T_TOK * 2];
__device__ int   g_ctr13;
__device__ int   g_ctr2;

__device__ __forceinline__ float silu_f(float v) { return v / (1.0f + expf(-v)); }

__device__ __forceinline__ uint32_t smem_u32(const void* p) {
    uint32_t a;
    asm("{ .reg .u64 t; cvta.to.shared.u64 t, %1; cvt.u32.u64 %0, t; }" : "=r"(a) : "l"(p));
    return a;
}

#define MBARRIER_INIT(a, c) \
    asm volatile("mbarrier.init.shared.b64 [%0], %1;" :: "r"((uint32_t)(a)), "r"((uint32_t)(c)) : "memory")
#define MBARRIER_EXPECT_TX(a, b) \
    asm volatile("mbarrier.arrive.expect_tx.shared.b64 _, [%0], %1;" :: "r"((uint32_t)(a)), "r"((uint32_t)(b)) : "memory")
#define MBAR_WAIT(a, ph) do { \
    uint32_t _m = (uint32_t)(a), _p = (uint32_t)(ph), _d; \
    asm volatile("{ .reg .pred p; mbarrier.try_wait.parity.acquire.cta.shared::cta.b64 p, [%1], %2; selp.b32 %0, 1, 0, p; }" \
        : "=r"(_d) : "r"(_m), "r"(_p) : "memory"); \
    if (!_d) asm volatile("{ .reg .pred P1; WL_%=: mbarrier.try_wait.parity.acquire.cta.shared::cta.b64 P1, [%0], %1, 0x989680; @P1 bra.uni WD_%=; bra.uni WL_%=; WD_%=: }" \
        :: "r"(_m), "r"(_p) : "memory"); } while (0)

#define TMA2D(sm, mp, c0, c1, mb) \
    asm volatile("cp.async.bulk.tensor.2d.shared::cta.global.tile.mbarrier::complete_tx::bytes [%0], [%1, {%2, %3}], [%4];" \
        :: "r"((uint32_t)(sm)), "l"(mp), "r"((int)(c0)), "r"((int)(c1)), "r"((uint32_t)(mb)) : "memory")
#define TMA3D(sm, mp, c0, c1, c2, mb) \
    asm volatile("cp.async.bulk.tensor.3d.shared::cta.global.tile.mbarrier::complete_tx::bytes [%0], [%1, {%2, %3, %4}], [%5];" \
        :: "r"((uint32_t)(sm)), "l"(mp), "r"((int)(c0)), "r"((int)(c1)), "r"((int)(c2)), "r"((uint32_t)(mb)) : "memory")

__device__ __forceinline__ float lds_f32(uint32_t a) {
    float v;
    asm volatile("ld.shared.f32 %0, [%1];" : "=f"(v) : "r"(a));
    return v;
}
__device__ __forceinline__ uint32_t pack_h2(float lo, float hi) {
    uint32_t d;
    asm("cvt.rn.f16x2.f32 %0, %1, %2;" : "=r"(d) : "f"(hi), "f"(lo));
    return d;
}
__device__ __forceinline__ void ldsm4(uint32_t& r0, uint32_t& r1, uint32_t& r2, uint32_t& r3,
                                      uint32_t addr) {
    asm volatile("ldmatrix.sync.aligned.m8n8.x4.shared.b16 {%0,%1,%2,%3}, [%4];"
        : "=r"(r0), "=r"(r1), "=r"(r2), "=r"(r3) : "r"(addr));
}
__device__ __forceinline__ void mma_f16(float& c0, float& c1, float& c2, float& c3,
                                        uint32_t a0, uint32_t a1, uint32_t a2, uint32_t a3,
                                        uint32_t b0, uint32_t b1) {
    asm volatile(
        "mma.sync.aligned.m16n8k16.row.col.f32.f16.f16.f32 "
        "{%0,%1,%2,%3}, {%4,%5,%6,%7}, {%8,%9}, {%0,%1,%2,%3};\n"
        : "+f"(c0), "+f"(c1), "+f"(c2), "+f"(c3)
        : "r"(a0), "r"(a1), "r"(a2), "r"(a3), "r"(b0), "r"(b1));
}

// ------------------------------- routing -----------------------------------
__global__ void gate_kernel(const float* __restrict__ x, const float* __restrict__ wg) {
    int t = blockIdx.x * (blockDim.x >> 5) + (threadIdx.x >> 5);
    int lane = threadIdx.x & 31;
    if (t >= T_TOK) return;
    const float* xr = x + (size_t)t * H_DIM;
    float acc[E_EXP];
#pragma unroll
    for (int e = 0; e < E_EXP; e++) acc[e] = 0.0f;
    for (int h = lane; h < H_DIM; h += 32) {
        float xv = xr[h];
        const float* wr = wg + (size_t)h * E_EXP;
#pragma unroll
        for (int e = 0; e < E_EXP; e++) acc[e] += xv * wr[e];
    }
#pragma unroll
    for (int e = 0; e < E_EXP; e++)
#pragma unroll
        for (int o = 16; o > 0; o >>= 1) acc[e] += __shfl_xor_sync(0xffffffffu, acc[e], o);
    if (lane == 0) {
        int i0 = 0; float v0 = acc[0];
#pragma unroll
        for (int e = 1; e < E_EXP; e++) if (acc[e] > v0) { v0 = acc[e]; i0 = e; }
        int i1 = -1; float v1 = -INFINITY;
#pragma unroll
        for (int e = 0; e < E_EXP; e++) if (e != i0 && acc[e] > v1) { v1 = acc[e]; i1 = e; }
        float w0 = 1.0f / (1.0f + expf(v1 - v0));
        g_te[2 * t] = i0;     g_tw[2 * t] = w0;
        g_te[2 * t + 1] = i1; g_tw[2 * t + 1] = 1.0f - w0;
    }
}

__global__ void route_scatter_kernel() {
    __shared__ int scnt[E_EXP], soff[E_EXP + 1], sfill[E_EXP];
    int tid = threadIdx.x;
    if (tid < E_EXP) { scnt[tid] = 0; sfill[tid] = 0; }
    if (tid == 0) { g_ctr13 = 0; g_ctr2 = 0; }
    __syncthreads();
    for (int i = tid; i < 2 * T_TOK; i += 256) atomicAdd(&scnt[g_te[i]], 1);
    __syncthreads();
    if (tid == 0) {
        int o = 0;
#pragma unroll
        for (int e = 0; e < E_EXP; e++) { soff[e] = o; o += (scnt[e] + 127) & ~127; }
        soff[E_EXP] = o;
#pragma unroll
        for (int e = 0; e <= E_EXP; e++) g_off[e] = soff[e];
    }
    __syncthreads();
    if (tid < MTILES) {
        int e = -1;
#pragma unroll
        for (int ee = 0; ee < E_EXP; ee++)
            if (tid * 128 >= soff[ee] && tid * 128 < soff[ee + 1]) e = ee;
        g_tile_e[tid] = e;
    }
    for (int r = tid; r < ROWS_CAP; r += 256) {
        g_rows[r] = 0;
        g_rw[r] = 0.0f;
    }
    __syncthreads();
    for (int t = tid; t < T_TOK; t += 256) {
#pragma unroll
        for (int s = 0; s < 2; s++) {
            int e = g_te[2 * t + s];
            int r = soff[e] + atomicAdd(&sfill[e], 1);
            g_rows[r] = t;
            g_rw[r] = g_tw[2 * t + s];
            g_pos[2 * t + s] = r;
        }
    }
}

__global__ void gather_kernel(const float* __restrict__ x) {
    int idx = blockIdx.x * blockDim.x + threadIdx.x;
    int r = idx >> 9;
    if (r >= g_off[E_EXP]) return;
    int h = (idx & 511) << 2;
    float4 v = *reinterpret_cast<const float4*>(x + (size_t)g_rows[r] * H_DIM + h);
    *reinterpret_cast<__half2*>(g_X + (size_t)r * H_DIM + h) = __floats2half2_rn(v.x, v.y);
    *reinterpret_cast<__half2*>(g_X + (size_t)r * H_DIM + h + 2) = __floats2half2_rn(v.z, v.w);
}

// ---------------------------------------------------------------------------
// GEMM1 fused, persistent TMA. Tile = (my, bn): 128x64, K=H (32 chunks of 64).
// 296 CTAs steal tiles via g_ctr13; 2-stage pipeline linearized across tiles.
// ---------------------------------------------------------------------------
__global__ __launch_bounds__(256, 2) void gemm13_kernel(
    const __grid_constant__ CUtensorMap tmA,
    const __grid_constant__ CUtensorMap tmB1,
    const __grid_constant__ CUtensorMap tmB3) {
    extern __shared__ uint32_t smem[];

    const int tid = threadIdx.x;
    const int warp = tid >> 5;
    const int lane = tid & 31;
    const int wm = warp & 3;
    const int wn = warp >> 2;
    const int g = lane >> 2;
    const int tg = lane & 3;

    const uint32_t sbase = smem_u32(smem);
    const uint32_t barb = sbase;
    int* slot = (int*)(smem + 4);
    const uint32_t tiles = (sbase + 64 + 1023) & ~1023u;

    if (tid == 0) {
        MBARRIER_INIT(barb, 1);
        MBARRIER_INIT(barb + 8, 1);
        int t;
        do { t = atomicAdd(&g_ctr13, 1); } while (t < NT13 && g_tile_e[t >> 6] < 0);
        slot[0] = (t < NT13) ? t : -1;
    }
    __syncthreads();
    int cur = slot[0];
    if (cur < 0) return;
    int my = cur >> 6, bn = (cur & 63) << 6, e = g_tile_e[my], bm = my << 7;

    if (tid == 0) {
        MBARRIER_EXPECT_TX(barb, STG13_B);
        TMA2D(tiles, &tmA, 0, bm, barb);
        TMA3D(tiles + 16384, &tmB1, bn, 0, e, barb);
        TMA3D(tiles + 24576, &tmB1, bn + 32, 0, e, barb);
        TMA3D(tiles + 32768, &tmB3, bn, 0, e, barb);
        TMA3D(tiles + 40960, &tmB3, bn + 32, 0, e, barb);
    }

    // lane-constant addressing (tile-independent)
    const int arow = wm * 32 + (lane & 15);
    const uint32_t alow = (uint32_t)((lane >> 4) * 16);
    uint32_t abasemi[2], axor[2];
#pragma unroll
    for (int mi = 0; mi < 2; mi++) {
        int r = arow + mi * 16;
        abasemi[mi] = (uint32_t)r << 7;
        axor[mi] = (uint32_t)(r & 7) << 4;
    }
    uint32_t bc0[4], bc1[4];
#pragma unroll
    for (int ni = 0; ni < 4; ni++) {
        uint32_t cb = (uint32_t)(ni * 8 + g) << 2;
        bc0[ni] = cb ^ ((uint32_t)(2 * tg) << 4);
        bc1[ni] = cb ^ ((uint32_t)(2 * tg + 1) << 4);
    }
    const uint32_t pb1 = tiles + 16384 + (uint32_t)wn * 8192;
    const uint32_t pb3 = tiles + 32768 + (uint32_t)wn * 8192;

    uint32_t gc = 0;
    const int kt = H_DIM / 64;  // 32

    for (;;) {
        float c1[2][4][4], c3[2][4][4];
#pragma unroll
        for (int mi = 0; mi < 2; mi++)
#pragma unroll
            for (int ni = 0; ni < 4; ni++)
#pragma unroll
                for (int q = 0; q < 4; q++) { c1[mi][ni][q] = 0.0f; c3[mi][ni][q] = 0.0f; }

        for (int it = 0; it < kt; it++) {
            MBAR_WAIT(barb + (gc & 1) * 8, (gc >> 1) & 1);
            __syncthreads();

            if (tid == 0) {
                const uint32_t nb = (gc + 1) & 1;
                const uint32_t st = tiles + nb * STG13_B;
                const uint32_t mb = barb + nb * 8;
                if (it + 1 < kt) {
                    const int k0 = (it + 1) * 64;
                    MBARRIER_EXPECT_TX(mb, STG13_B);
                    TMA2D(st, &tmA, k0, bm, mb);
                    TMA3D(st + 16384, &tmB1, bn, k0, e, mb);
                    TMA3D(st + 24576, &tmB1, bn + 32, k0, e, mb);
                    TMA3D(st + 32768, &tmB3, bn, k0, e, mb);
                    TMA3D(st + 40960, &tmB3, bn + 32, k0, e, mb);
                } else {
                    int t;
                    do { t = atomicAdd(&g_ctr13, 1); } while (t < NT13 && g_tile_e[t >> 6] < 0);
                    t = (t < NT13) ? t : -1;
                    slot[0] = t;
                    if (t >= 0) {
                        int nmy = t >> 6, nbn = (t & 63) << 6;
                        int ne = g_tile_e[nmy], nbm = nmy << 7;
                        MBARRIER_EXPECT_TX(mb, STG13_B);
                        TMA2D(st, &tmA, 0, nbm, mb);
                        TMA3D(st + 16384, &tmB1, nbn, 0, ne, mb);
                        TMA3D(st + 24576, &tmB1, nbn + 32, 0, ne, mb);
                        TMA3D(st + 32768, &tmB3, nbn, 0, ne, mb);
                        TMA3D(st + 40960, &tmB3, nbn + 32, 0, ne, mb);
                    }
                }
            }

            const uint32_t soff = (gc & 1) * STG13_B;
            const uint32_t ab = tiles + soff;
#pragma unroll
            for (int ks = 0; ks < 4; ks++) {
                uint32_t a[2][4];
#pragma unroll
                for (int mi = 0; mi < 2; mi++) {
                    uint32_t ad = ab + abasemi[mi]
                                + ((((uint32_t)ks << 5) | alow) ^ axor[mi]);
                    ldsm4(a[mi][0], a[mi][1], a[mi][2], a[mi][3], ad);
                }
                const uint32_t rbyte = (uint32_t)(16 * ks + 2 * tg) << 7;
                const uint32_t r1b = pb1 + soff + rbyte;
                const uint32_t r3b = pb3 + soff + rbyte;
#pragma unroll
                for (int ni = 0; ni < 4; ni++) {
                    float f0 = lds_f32(r1b + bc0[ni]);
                    float f1 = lds_f32(r1b + 128 + bc1[ni]);
                    float f2 = lds_f32(r1b + 1024 + bc0[ni]);
                    float f3 = lds_f32(r1b + 1152 + bc1[ni]);
                    uint32_t b10 = pack_h2(f0, f1);
                    uint32_t b11 = pack_h2(f2, f3);
                    float h0 = lds_f32(r3b + bc0[ni]);
                    float h1 = lds_f32(r3b + 128 + bc1[ni]);
                    float h2 = lds_f32(r3b + 1024 + bc0[ni]);
                    float h3 = lds_f32(r3b + 1152 + bc1[ni]);
                    uint32_t b30 = pack_h2(h0, h1);
                    uint32_t b31 = pack_h2(h2, h3);
#pragma unroll
                    for (int mi = 0; mi < 2; mi++) {
                        mma_f16(c1[mi][ni][0], c1[mi][ni][1], c1[mi][ni][2], c1[mi][ni][3],
                                a[mi][0], a[mi][1], a[mi][2], a[mi][3], b10, b11);
                        mma_f16(c3[mi][ni][0], c3[mi][ni][1], c3[mi][ni][2], c3[mi][ni][3],
                                a[mi][0], a[mi][1], a[mi][2], a[mi][3], b30, b31);
                    }
                }
            }
            gc++;
        }

        // epilogue (R8-verified, 4M x 2N)
        const int r_base = bm + wm * 32;
        const int c_base = bn + wn * 32;
#pragma unroll
        for (int mi = 0; mi < 2; mi++) {
            int r0 = r_base + mi * 16 + g;
            float wa = g_rw[r0];
            float wb = g_rw[r0 + 8];
            size_t o0 = (size_t)r0 * F_DIM;
            size_t o1 = (size_t)(r0 + 8) * F_DIM;
#pragma unroll
            for (int ni = 0; ni < 4; ni++) {
                int cl = c_base + ni * 8 + 2 * tg;
                __half2 v0 = __floats2half2_rn(silu_f(c1[mi][ni][0]) * c3[mi][ni][0] * wa,
                                               silu_f(c1[mi][ni][1]) * c3[mi][ni][1] * wa);
                __half2 v1 = __floats2half2_rn(silu_f(c1[mi][ni][2]) * c3[mi][ni][2] * wb,
                                               silu_f(c1[mi][ni][3]) * c3[mi][ni][3] * wb);
                *reinterpret_cast<__half2*>(g_A + o0 + cl) = v0;
                *reinterpret_cast<__half2*>(g_A + o1 + cl) = v1;
            }
        }

        __syncthreads();          // publish slot[0] written at it==kt-1
        int nxt = slot[0];
        if (nxt < 0) break;
        cur = nxt;
        my = cur >> 6; bn = (cur & 63) << 6; e = g_tile_e[my]; bm = my << 7;
    }
}

// ---------------------------------------------------------------------------
// GEMM2, persistent TMA. Tile = (z, my, bn): 128x128, K-slice 1024 (16 chunks).
// ---------------------------------------------------------------------------
__global__ __launch_bounds__(256, 2) void gemm2_kernel(
    const __grid_constant__ CUtensorMap tmA2,
    const __grid_constant__ CUtensorMap tmB2) {
    extern __shared__ uint32_t smem[];

    const int tid = threadIdx.x;
    const int warp = tid >> 5;
    const int lane = tid & 31;
    const int wm = warp & 3;
    const int wn = warp >> 2;
    const int g = lane >> 2;
    const int tg = lane & 3;

    const uint32_t sbase = smem_u32(smem);
    const uint32_t barb = sbase;
    int* slot = (int*)(smem + 4);
    const uint32_t tiles = (sbase + 64 + 1023) & ~1023u;

    if (tid == 0) {
        MBARRIER_INIT(barb, 1);
        MBARRIER_INIT(barb + 8, 1);
        int t;
        do { t = atomicAdd(&g_ctr2, 1); } while (t < NT2 && g_tile_e[(t >> 4) % MTILES] < 0);
        slot[0] = (t < NT2) ? t : -1;
    }
    __syncthreads();
    int cur = slot[0];
    if (cur < 0) return;
    int bn = (cur & 15) << 7;
    int zm = cur >> 4;
    int my = zm % MTILES, z = zm / MTILES;
    int e = g_tile_e[my], bm = my << 7, kb = z * (F_DIM / KSPLIT);

    if (tid == 0) {
        MBARRIER_EXPECT_TX(barb, STG2_B);
        TMA2D(tiles, &tmA2, kb, bm, barb);
#pragma unroll
        for (int p = 0; p < 4; p++)
            TMA3D(tiles + 16384 + p * 8192, &tmB2, bn + p * 32, kb, e, barb);
    }

    const int arow = wm * 32 + (lane & 15);
    const uint32_t alow = (uint32_t)((lane >> 4) * 16);
    uint32_t abasemi[2], axor[2];
#pragma unroll
    for (int mi = 0; mi < 2; mi++) {
        int r = arow + mi * 16;
        abasemi[mi] = (uint32_t)r << 7;
        axor[mi] = (uint32_t)(r & 7) << 4;
    }
    uint32_t bc0[4], bc1[4];
#pragma unroll
    for (int nj = 0; nj < 4; nj++) {
        uint32_t cb = (uint32_t)(nj * 8 + g) << 2;
        bc0[nj] = cb ^ ((uint32_t)(2 * tg) << 4);
        bc1[nj] = cb ^ ((uint32_t)(2 * tg + 1) << 4);
    }
    const uint32_t pb0 = tiles + 16384 + (uint32_t)(2 * wn) * 8192;
    const uint32_t pb1p = pb0 + 8192;

    uint32_t gc = 0;
    const int kt = (F_DIM / KSPLIT) / 64;   // 16

    for (;;) {
        float c[2][8][4];
#pragma unroll
        for (int mi = 0; mi < 2; mi++)
#pragma unroll
            for (int ni = 0; ni < 8; ni++)
#pragma unroll
                for (int q = 0; q < 4; q++) c[mi][ni][q] = 0.0f;

        for (int it = 0; it < kt; it++) {
            MBAR_WAIT(barb + (gc & 1) * 8, (gc >> 1) & 1);
            __syncthreads();

            if (tid == 0) {
                const uint32_t nb = (gc + 1) & 1;
                const uint32_t st = tiles + nb * STG2_B;
                const uint32_t mb = barb + nb * 8;
                if (it + 1 < kt) {
                    const int k0 = kb + (it + 1) * 64;
                    MBARRIER_EXPECT_TX(mb, STG2_B);
                    TMA2D(st, &tmA2, k0, bm, mb);
#pragma unroll
                    for (int p = 0; p < 4; p++)
                        TMA3D(st + 16384 + p * 8192, &tmB2, bn + p * 32, k0, e, mb);
                } else {
                    int t;
                    do { t = atomicAdd(&g_ctr2, 1); } while (t < NT2 && g_tile_e[(t >> 4) % MTILES] < 0);
                    t = (t < NT2) ? t : -1;
                    slot[0] = t;
                    if (t >= 0) {
                        int nbn = (t & 15) << 7;
                        int nzm = t >> 4;
                        int nmy = nzm % MTILES, nz = nzm / MTILES;
                        int ne = g_tile_e[nmy], nbm = nmy << 7, nkb = nz * (F_DIM / KSPLIT);
                        MBARRIER_EXPECT_TX(mb, STG2_B);
                        TMA2D(st, &tmA2, nkb, nbm, mb);
#pragma unroll
                        for (int p = 0; p < 4; p++)
                            TMA3D(st + 16384 + p * 8192, &tmB2, nbn + p * 32, nkb, ne, mb);
                    }
                }
            }

            const uint32_t soff = (gc & 1) * STG2_B;
            const uint32_t ab = tiles + soff;
#pragma unroll
            for (int ks = 0; ks < 4; ks++) {
                uint32_t a[2][4];
#pragma unroll
                for (int mi = 0; mi < 2; mi++) {
                    uint32_t ad = ab + abasemi[mi]
                                + ((((uint32_t)ks << 5) | alow) ^ axor[mi]);
                    ldsm4(a[mi][0], a[mi][1], a[mi][2], a[mi][3], ad);
                }
                const uint32_t rbyte = (uint32_t)(16 * ks + 2 * tg) << 7;
                const uint32_t rp0 = pb0 + soff + rbyte;
                const uint32_t rp1 = pb1p + soff + rbyte;
#pragma unroll
                for (int ni = 0; ni < 8; ni++) {
                    const uint32_t rp = (ni < 4) ? rp0 : rp1;
                    const int nj = ni & 3;
                    float f0 = lds_f32(rp + bc0[nj]);
                    float f1 = lds_f32(rp + 128 + bc1[nj]);
                    float f2 = lds_f32(rp + 1024 + bc0[nj]);
                    float f3 = lds_f32(rp + 1152 + bc1[nj]);
                    uint32_t b0 = pack_h2(f0, f1);
                    uint32_t b1 = pack_h2(f2, f3);
#pragma unroll
                    for (int mi = 0; mi < 2; mi++)
                        mma_f16(c[mi][ni][0], c[mi][ni][1], c[mi][ni][2], c[mi][ni][3],
                                a[mi][0], a[mi][1], a[mi][2], a[mi][3], b0, b1);
                }
            }
            gc++;
        }

        float* Yp = g_Y + (size_t)z * ((size_t)ROWS_CAP * H_DIM);
        const int r_base = bm + wm * 32;
        const int c_base = bn + wn * 64;
#pragma unroll
        for (int mi = 0; mi < 2; mi++) {
            int r0 = r_base + mi * 16 + g;
            size_t o0 = (size_t)r0 * H_DIM;
            size_t o1 = (size_t)(r0 + 8) * H_DIM;
#pragma unroll
            for (int ni = 0; ni < 8; ni++) {
                int cl = c_base + ni * 8 + 2 * tg;
                *reinterpret_cast<float2*>(Yp + o0 + cl) = make_float2(c[mi][ni][0], c[mi][ni][1]);
                *reinterpret_cast<float2*>(Yp + o1 + cl) = make_float2(c[mi][ni][2], c[mi][ni][3]);
            }
        }

        __syncthreads();
        int nxt = slot[0];
        if (nxt < 0) break;
        cur = nxt;
        bn = (cur & 15) << 7;
        zm = cur >> 4;
        my = zm % MTILES; z = zm / MTILES;
        e = g_tile_e[my]; bm = my << 7; kb = z * (F_DIM / KSPLIT);
    }
}

__global__ void combine_kernel(float* __restrict__ out) {
    int i = blockIdx.x * blockDim.x + threadIdx.x;
    int t = i >> 9;
    int h = (i & 511) << 2;
    size_t r0 = (size_t)g_pos[2 * t] * H_DIM + h;
    size_t r1 = (size_t)g_pos[2 * t + 1] * H_DIM + h;
    const size_t SL = (size_t)ROWS_CAP * H_DIM;
    float4 s0 = make_float4(0.f, 0.f, 0.f, 0.f);
    float4 s1 = make_float4(0.f, 0.f, 0.f, 0.f);
#pragma unroll
    for (int zz = 0; zz < KSPLIT; zz++) {
        float4 a = *reinterpret_cast<const float4*>(g_Y + zz * SL + r0);
        float4 b = *reinterpret_cast<const float4*>(g_Y + zz * SL + r1);
        s0.x += a.x; s0.y += a.y; s0.z += a.z; s0.w += a.w;
        s1.x += b.x; s1.y += b.y; s1.z += b.z; s1.w += b.w;
    }
    *reinterpret_cast<float4*>(out + (size_t)t * H_DIM + h) =
        make_float4(s0.x + s1.x, s0.y + s1.y, s0.z + s1.z, s0.w + s1.w);
}

// ------------------------------- host --------------------------------------
typedef CUresult (*encode_fn_t)(CUtensorMap*, CUtensorMapDataType, unsigned, void*,
                                const unsigned long long*, const unsigned long long*,
                                const unsigned*, const unsigned*, CUtensorMapInterleave,
                                CUtensorMapSwizzle, CUtensorMapL2promotion,
                                CUtensorMapFloatOOBfill);

extern "C" void kernel_launch(void* const* d_in, const int* in_sizes, int n_in,
                              void* d_out, int out_size) {
    const float* x  = (const float*)d_in[0];
    const float* wg = (const float*)d_in[1];
    const float* w1 = (const float*)d_in[2];
    const float* w3 = (const float*)d_in[3];
    const float* w2 = (const float*)d_in[4];
    float* out = (float*)d_out;

    void* encp = nullptr;
    cudaDriverEntryPointQueryResult qr;
    cudaGetDriverEntryPoint("cuTensorMapEncodeTiled", &encp, cudaEnableDefault, &qr);
    encode_fn_t enc = (encode_fn_t)encp;

    void* pX = nullptr; cudaGetSymbolAddress(&pX, g_X);
    void* pA = nullptr; cudaGetSymbolAddress(&pA, g_A);

    CUtensorMap tmA, tmA2;
    {
        unsigned long long dims[2] = {H_DIM, ROWS_CAP};
        unsigned long long strides[1] = {H_DIM * 2ull};
        unsigned box[2] = {64u, 128u};
        unsigned es[2] = {1u, 1u};
        enc(&tmA, CU_TENSOR_MAP_DATA_TYPE_FLOAT16, 2, pX, dims, strides, box, es,
            CU_TENSOR_MAP_INTERLEAVE_NONE, CU_TENSOR_MAP_SWIZZLE_128B,
            CU_TENSOR_MAP_L2_PROMOTION_L2_128B, CU_TENSOR_MAP_FLOAT_OOB_FILL_NONE);
        unsigned long long dims2[2] = {F_DIM, ROWS_CAP};
        unsigned long long strides2[1] = {F_DIM * 2ull};
        enc(&tmA2, CU_TENSOR_MAP_DATA_TYPE_FLOAT16, 2, pA, dims2, strides2, box, es,
            CU_TENSOR_MAP_INTERLEAVE_NONE, CU_TENSOR_MAP_SWIZZLE_128B,
            CU_TENSOR_MAP_L2_PROMOTION_L2_128B, CU_TENSOR_MAP_FLOAT_OOB_FILL_NONE);
    }
    CUtensorMap tmW1, tmW3, tmW2;
    {
        unsigned long long dims[3] = {F_DIM, H_DIM, E_EXP};
        unsigned long long strides[2] = {F_DIM * 4ull, (unsigned long long)F_DIM * H_DIM * 4ull};
        unsigned box[3] = {32u, 64u, 1u};
        unsigned es[3] = {1u, 1u, 1u};
        enc(&tmW1, CU_TENSOR_MAP_DATA_TYPE_FLOAT32, 3, (void*)w1, dims, strides, box, es,
            CU_TENSOR_MAP_INTERLEAVE_NONE, CU_TENSOR_MAP_SWIZZLE_128B,
            CU_TENSOR_MAP_L2_PROMOTION_L2_128B, CU_TENSOR_MAP_FLOAT_OOB_FILL_NONE);
        enc(&tmW3, CU_TENSOR_MAP_DATA_TYPE_FLOAT32, 3, (void*)w3, dims, strides, box, es,
            CU_TENSOR_MAP_INTERLEAVE_NONE, CU_TENSOR_MAP_SWIZZLE_128B,
            CU_TENSOR_MAP_L2_PROMOTION_L2_128B, CU_TENSOR_MAP_FLOAT_OOB_FILL_NONE);
        unsigned long long dims2[3] = {H_DIM, F_DIM, E_EXP};
        unsigned long long strides2[2] = {H_DIM * 4ull, (unsigned long long)H_DIM * F_DIM * 4ull};
        enc(&tmW2, CU_TENSOR_MAP_DATA_TYPE_FLOAT32, 3, (void*)w2, dims2, strides2, box, es,
            CU_TENSOR_MAP_INTERLEAVE_NONE, CU_TENSOR_MAP_SWIZZLE_128B,
            CU_TENSOR_MAP_L2_PROMOTION_L2_128B, CU_TENSOR_MAP_FLOAT_OOB_FILL_NONE);
    }

    cudaFuncSetAttribute(gemm13_kernel, cudaFuncAttributeMaxDynamicSharedMemorySize, SMEM13);
    cudaFuncSetAttribute(gemm2_kernel, cudaFuncAttributeMaxDynamicSharedMemorySize, SMEM2);

    gate_kernel<<<T_TOK / 8, 256>>>(x, wg);
    route_scatter_kernel<<<1, 256>>>();
    gather_kernel<<<ROWS_CAP * 512 / 256, 256>>>(x);

    gemm13_kernel<<<NCTA, 256, SMEM13>>>(tmA, tmW1, tmW3);
    gemm2_kernel<<<NCTA, 256, SMEM2>>>(tmA2, tmW2);

    combine_kernel<<<(T_TOK * H_DIM / 4) / 256, 256>>>(out);
}

// round 17
// speedup vs baseline: 1.0978x; 1.0978x over previous
#include <cuda_runtime.h>
#include <cuda.h>
#include <cuda_fp16.h>
#include <stdint.h>
#include <math.h>

#define T_TOK 1024
#define H_DIM 2048
#define F_DIM 4096
#define E_EXP 8
#define ROWS_CAP 3072
#define MTILES (ROWS_CAP / 128)   // 24
#define KSPLIT 4

#define STG13_B 49152u
#define SMEM13 (1024 + 64 + 2 * 49152)
#define STG2_B 49152u
#define SMEM2 (1024 + 64 + 2 * 49152)

// ---------------- scratch ----------------
__device__ __align__(256) __half g_X[(size_t)ROWS_CAP * H_DIM];
__device__ __align__(256) __half g_A[(size_t)ROWS_CAP * F_DIM];
__device__ __align__(256) float  g_Y[(size_t)KSPLIT * ROWS_CAP * H_DIM];
__device__ int   g_off[E_EXP + 1];
__device__ int   g_tile_e[MTILES];
__device__ int   g_rows[ROWS_CAP];
__device__ float g_rw[ROWS_CAP];
__device__ int   g_pos[T_TOK * 2];
__device__ int   g_te[T_TOK * 2];
__device__ float g_tw[T_TOK * 2];

__device__ __forceinline__ float silu_f(float v) { return v / (1.0f + expf(-v)); }

__device__ __forceinline__ uint32_t smem_u32(const void* p) {
    uint32_t a;
    asm("{ .reg .u64 t; cvta.to.shared.u64 t, %1; cvt.u32.u64 %0, t; }" : "=r"(a) : "l"(p));
    return a;
}

#define MBARRIER_INIT(a, c) \
    asm volatile("mbarrier.init.shared.b64 [%0], %1;" :: "r"((uint32_t)(a)), "r"((uint32_t)(c)) : "memory")
#define MBARRIER_EXPECT_TX(a, b) \
    asm volatile("mbarrier.arrive.expect_tx.shared.b64 _, [%0], %1;" :: "r"((uint32_t)(a)), "r"((uint32_t)(b)) : "memory")
#define MBAR_WAIT(a, ph) do { \
    uint32_t _m = (uint32_t)(a), _p = (uint32_t)(ph), _d; \
    asm volatile("{ .reg .pred p; mbarrier.try_wait.parity.acquire.cta.shared::cta.b64 p, [%1], %2; selp.b32 %0, 1, 0, p; }" \
        : "=r"(_d) : "r"(_m), "r"(_p) : "memory"); \
    if (!_d) asm volatile("{ .reg .pred P1; WL_%=: mbarrier.try_wait.parity.acquire.cta.shared::cta.b64 P1, [%0], %1, 0x989680; @P1 bra.uni WD_%=; bra.uni WL_%=; WD_%=: }" \
        :: "r"(_m), "r"(_p) : "memory"); } while (0)

#define TMA2D(sm, mp, c0, c1, mb) \
    asm volatile("cp.async.bulk.tensor.2d.shared::cta.global.tile.mbarrier::complete_tx::bytes [%0], [%1, {%2, %3}], [%4];" \
        :: "r"((uint32_t)(sm)), "l"(mp), "r"((int)(c0)), "r"((int)(c1)), "r"((uint32_t)(mb)) : "memory")
#define TMA3D(sm, mp, c0, c1, c2, mb) \
    asm volatile("cp.async.bulk.tensor.3d.shared::cta.global.tile.mbarrier::complete_tx::bytes [%0], [%1, {%2, %3, %4}], [%5];" \
        :: "r"((uint32_t)(sm)), "l"(mp), "r"((int)(c0)), "r"((int)(c1)), "r"((int)(c2)), "r"((uint32_t)(mb)) : "memory")

__device__ __forceinline__ float lds_f32(uint32_t a) {
    float v;
    asm volatile("ld.shared.f32 %0, [%1];" : "=f"(v) : "r"(a));
    return v;
}
__device__ __forceinline__ uint32_t pack_h2(float lo, float hi) {
    uint32_t d;
    asm("cvt.rn.f16x2.f32 %0, %1, %2;" : "=r"(d) : "f"(hi), "f"(lo));
    return d;
}
__device__ __forceinline__ void ldsm4(uint32_t& r0, uint32_t& r1, uint32_t& r2, uint32_t& r3,
                                      uint32_t addr) {
    asm volatile("ldmatrix.sync.aligned.m8n8.x4.shared.b16 {%0,%1,%2,%3}, [%4];"
        : "=r"(r0), "=r"(r1), "=r"(r2), "=r"(r3) : "r"(addr));
}
__device__ __forceinline__ void mma_f16(float& c0, float& c1, float& c2, float& c3,
                                        uint32_t a0, uint32_t a1, uint32_t a2, uint32_t a3,
                                        uint32_t b0, uint32_t b1) {
    asm volatile(
        "mma.sync.aligned.m16n8k16.row.col.f32.f16.f16.f32 "
        "{%0,%1,%2,%3}, {%4,%5,%6,%7}, {%8,%9}, {%0,%1,%2,%3};\n"
        : "+f"(c0), "+f"(c1), "+f"(c2), "+f"(c3)
        : "r"(a0), "r"(a1), "r"(a2), "r"(a3), "r"(b0), "r"(b1));
}

// ------------------------------- routing -----------------------------------
__global__ void gate_kernel(const float* __restrict__ x, const float* __restrict__ wg) {
    int t = blockIdx.x * (blockDim.x >> 5) + (threadIdx.x >> 5);
    int lane = threadIdx.x & 31;
    if (t >= T_TOK) return;
    const float* xr = x + (size_t)t * H_DIM;
    float acc[E_EXP];
#pragma unroll
    for (int e = 0; e < E_EXP; e++) acc[e] = 0.0f;
    for (int h = lane; h < H_DIM; h += 32) {
        float xv = xr[h];
        const float* wr = wg + (size_t)h * E_EXP;
#pragma unroll
        for (int e = 0; e < E_EXP; e++) acc[e] += xv * wr[e];
    }
#pragma unroll
    for (int e = 0; e < E_EXP; e++)
#pragma unroll
        for (int o = 16; o > 0; o >>= 1) acc[e] += __shfl_xor_sync(0xffffffffu, acc[e], o);
    if (lane == 0) {
        int i0 = 0; float v0 = acc[0];
#pragma unroll
        for (int e = 1; e < E_EXP; e++) if (acc[e] > v0) { v0 = acc[e]; i0 = e; }
        int i1 = -1; float v1 = -INFINITY;
#pragma unroll
        for (int e = 0; e < E_EXP; e++) if (e != i0 && acc[e] > v1) { v1 = acc[e]; i1 = e; }
        float w0 = 1.0f / (1.0f + expf(v1 - v0));
        g_te[2 * t] = i0;     g_tw[2 * t] = w0;
        g_te[2 * t + 1] = i1; g_tw[2 * t + 1] = 1.0f - w0;
    }
}

__global__ void route_scatter_kernel() {
    __shared__ int scnt[E_EXP], soff[E_EXP + 1], sfill[E_EXP];
    int tid = threadIdx.x;
    if (tid < E_EXP) { scnt[tid] = 0; sfill[tid] = 0; }
    __syncthreads();
    for (int i = tid; i < 2 * T_TOK; i += 256) atomicAdd(&scnt[g_te[i]], 1);
    __syncthreads();
    if (tid == 0) {
        int o = 0;
#pragma unroll
        for (int e = 0; e < E_EXP; e++) { soff[e] = o; o += (scnt[e] + 127) & ~127; }
        soff[E_EXP] = o;
#pragma unroll
        for (int e = 0; e <= E_EXP; e++) g_off[e] = soff[e];
    }
    __syncthreads();
    if (tid < MTILES) {
        int e = -1;
#pragma unroll
        for (int ee = 0; ee < E_EXP; ee++)
            if (tid * 128 >= soff[ee] && tid * 128 < soff[ee + 1]) e = ee;
        g_tile_e[tid] = e;
    }
    for (int r = tid; r < ROWS_CAP; r += 256) {
        g_rows[r] = 0;
        g_rw[r] = 0.0f;
    }
    __syncthreads();
    for (int t = tid; t < T_TOK; t += 256) {
#pragma unroll
        for (int s = 0; s < 2; s++) {
            int e = g_te[2 * t + s];
            int r = soff[e] + atomicAdd(&sfill[e], 1);
            g_rows[r] = t;
            g_rw[r] = g_tw[2 * t + s];
            g_pos[2 * t + s] = r;
        }
    }
}

__global__ void gather_kernel(const float* __restrict__ x) {
    int idx = blockIdx.x * blockDim.x + threadIdx.x;
    int r = idx >> 9;
    if (r >= g_off[E_EXP]) return;
    int h = (idx & 511) << 2;
    float4 v = *reinterpret_cast<const float4*>(x + (size_t)g_rows[r] * H_DIM + h);
    *reinterpret_cast<__half2*>(g_X + (size_t)r * H_DIM + h) = __floats2half2_rn(v.x, v.y);
    *reinterpret_cast<__half2*>(g_X + (size_t)r * H_DIM + h + 2) = __floats2half2_rn(v.z, v.w);
}

// ---------------------------------------------------------------------------
// GEMM1 fused, TMA, 2M x 4N warp layout (warp tile 64x16 per matrix, mi=4).
// Block 128x64xK64. Stage: A fp16 SW128 + B1/B3 f32 SW128 (2 panels each).
// ---------------------------------------------------------------------------
__global__ __launch_bounds__(256, 2) void gemm13_kernel(
    const __grid_constant__ CUtensorMap tmA,
    const __grid_constant__ CUtensorMap tmB1,
    const __grid_constant__ CUtensorMap tmB3) {
    extern __shared__ uint32_t smem[];

    const int my = blockIdx.y;
    const int e = g_tile_e[my];
    if (e < 0) return;

    const int tid = threadIdx.x;
    const int warp = tid >> 5;
    const int lane = tid & 31;
    const int wm = warp & 1;       // 2 M groups of 64 rows
    const int wn = warp >> 1;      // 4 N groups of 16 cols
    const int g = lane >> 2;
    const int tg = lane & 3;

    const int bm = my * 128;
    const int bn = blockIdx.x * 64;

    const uint32_t sbase = smem_u32(smem);
    const uint32_t barb = sbase;
    const uint32_t tiles = (sbase + 64 + 1023) & ~1023u;

    if (tid == 0) {
        MBARRIER_INIT(barb, 1);
        MBARRIER_INIT(barb + 8, 1);
    }
    __syncthreads();

    if (tid == 0) {
        MBARRIER_EXPECT_TX(barb, STG13_B);
        TMA2D(tiles, &tmA, 0, bm, barb);
        TMA3D(tiles + 16384, &tmB1, bn, 0, e, barb);
        TMA3D(tiles + 24576, &tmB1, bn + 32, 0, e, barb);
        TMA3D(tiles + 32768, &tmB3, bn, 0, e, barb);
        TMA3D(tiles + 40960, &tmB3, bn + 32, 0, e, barb);
    }

    float c1[4][2][4], c3[4][2][4];
#pragma unroll
    for (int mi = 0; mi < 4; mi++)
#pragma unroll
        for (int ni = 0; ni < 2; ni++)
#pragma unroll
            for (int q = 0; q < 4; q++) { c1[mi][ni][q] = 0.0f; c3[mi][ni][q] = 0.0f; }

    // lane-constant addressing
    const int arow = wm * 64 + (lane & 15);
    const uint32_t alow = (uint32_t)((lane >> 4) * 16);
    uint32_t abasemi[4], axor[4];
#pragma unroll
    for (int mi = 0; mi < 4; mi++) {
        int r = arow + mi * 16;
        abasemi[mi] = (uint32_t)r << 7;
        axor[mi] = (uint32_t)(r & 7) << 4;
    }
    uint32_t bc0[2], bc1[2];
#pragma unroll
    for (int ni = 0; ni < 2; ni++) {
        uint32_t cb = (uint32_t)((wn & 1) * 16 + ni * 8 + g) << 2;   // col byte in panel
        bc0[ni] = cb ^ ((uint32_t)(2 * tg) << 4);
        bc1[ni] = cb ^ ((uint32_t)(2 * tg + 1) << 4);
    }
    const uint32_t pb1 = tiles + 16384 + (uint32_t)(wn >> 1) * 8192;
    const uint32_t pb3 = tiles + 32768 + (uint32_t)(wn >> 1) * 8192;

    const int kt = H_DIM / 64;  // 32

    for (int it = 0; it < kt; it++) {
        MBAR_WAIT(barb + (it & 1) * 8, (it >> 1) & 1);
        __syncthreads();

        if (tid == 0 && it + 1 < kt) {
            const uint32_t st = tiles + (uint32_t)((it + 1) & 1) * STG13_B;
            const uint32_t mb = barb + ((it + 1) & 1) * 8;
            const int k0 = (it + 1) * 64;
            MBARRIER_EXPECT_TX(mb, STG13_B);
            TMA2D(st, &tmA, k0, bm, mb);
            TMA3D(st + 16384, &tmB1, bn, k0, e, mb);
            TMA3D(st + 24576, &tmB1, bn + 32, k0, e, mb);
            TMA3D(st + 32768, &tmB3, bn, k0, e, mb);
            TMA3D(st + 40960, &tmB3, bn + 32, k0, e, mb);
        }

        const uint32_t soff = (uint32_t)(it & 1) * STG13_B;
        const uint32_t ab = tiles + soff;
#pragma unroll
        for (int ks = 0; ks < 4; ks++) {
            uint32_t a[4][4];
#pragma unroll
            for (int mi = 0; mi < 4; mi++) {
                uint32_t ad = ab + abasemi[mi]
                            + ((((uint32_t)ks << 5) | alow) ^ axor[mi]);
                ldsm4(a[mi][0], a[mi][1], a[mi][2], a[mi][3], ad);
            }
            const uint32_t rbyte = (uint32_t)(16 * ks + 2 * tg) << 7;
            const uint32_t r1b = pb1 + soff + rbyte;
            const uint32_t r3b = pb3 + soff + rbyte;
#pragma unroll
            for (int ni = 0; ni < 2; ni++) {
                float f0 = lds_f32(r1b + bc0[ni]);
                float f1 = lds_f32(r1b + 128 + bc1[ni]);
                float f2 = lds_f32(r1b + 1024 + bc0[ni]);
                float f3 = lds_f32(r1b + 1152 + bc1[ni]);
                uint32_t b10 = pack_h2(f0, f1);
                uint32_t b11 = pack_h2(f2, f3);
                float h0 = lds_f32(r3b + bc0[ni]);
                float h1 = lds_f32(r3b + 128 + bc1[ni]);
                float h2 = lds_f32(r3b + 1024 + bc0[ni]);
                float h3 = lds_f32(r3b + 1152 + bc1[ni]);
                uint32_t b30 = pack_h2(h0, h1);
                uint32_t b31 = pack_h2(h2, h3);
#pragma unroll
                for (int mi = 0; mi < 4; mi++) {
                    mma_f16(c1[mi][ni][0], c1[mi][ni][1], c1[mi][ni][2], c1[mi][ni][3],
                            a[mi][0], a[mi][1], a[mi][2], a[mi][3], b10, b11);
                    mma_f16(c3[mi][ni][0], c3[mi][ni][1], c3[mi][ni][2], c3[mi][ni][3],
                            a[mi][0], a[mi][1], a[mi][2], a[mi][3], b30, b31);
                }
            }
        }
    }

    // epilogue (2M x 4N)
    const int r_base = bm + wm * 64;
    const int c_base = bn + wn * 16;
#pragma unroll
    for (int mi = 0; mi < 4; mi++) {
        int r0 = r_base + mi * 16 + g;
        float wa = g_rw[r0];
        float wb = g_rw[r0 + 8];
        size_t o0 = (size_t)r0 * F_DIM;
        size_t o1 = (size_t)(r0 + 8) * F_DIM;
#pragma unroll
        for (int ni = 0; ni < 2; ni++) {
            int cl = c_base + ni * 8 + 2 * tg;
            __half2 v0 = __floats2half2_rn(silu_f(c1[mi][ni][0]) * c3[mi][ni][0] * wa,
                                           silu_f(c1[mi][ni][1]) * c3[mi][ni][1] * wa);
            __half2 v1 = __floats2half2_rn(silu_f(c1[mi][ni][2]) * c3[mi][ni][2] * wb,
                                           silu_f(c1[mi][ni][3]) * c3[mi][ni][3] * wb);
            *reinterpret_cast<__half2*>(g_A + o0 + cl) = v0;
            *reinterpret_cast<__half2*>(g_A + o1 + cl) = v1;
        }
    }
}

// ---------------------------------------------------------------------------
// GEMM2, TMA, 2M x 4N (warp tile 64x32 = one 32-col panel per warp, mi=4).
// Block 128x128xK64, K-split 4.
// ---------------------------------------------------------------------------
__global__ __launch_bounds__(256, 2) void gemm2_kernel(
    const __grid_constant__ CUtensorMap tmA2,
    const __grid_constant__ CUtensorMap tmB2) {
    extern __shared__ uint32_t smem[];

    const int my = blockIdx.y;
    const int e = g_tile_e[my];
    if (e < 0) return;
    const int z = blockIdx.z;

    const int tid = threadIdx.x;
    const int warp = tid >> 5;
    const int lane = tid & 31;
    const int wm = warp & 1;
    const int wn = warp >> 1;      // panel index 0..3
    const int g = lane >> 2;
    const int tg = lane & 3;

    const int bm = my * 128;
    const int bn = blockIdx.x * 128;
    const int kbase = z * (F_DIM / KSPLIT);

    const uint32_t sbase = smem_u32(smem);
    const uint32_t barb = sbase;
    const uint32_t tiles = (sbase + 64 + 1023) & ~1023u;

    if (tid == 0) {
        MBARRIER_INIT(barb, 1);
        MBARRIER_INIT(barb + 8, 1);
    }
    __syncthreads();

    if (tid == 0) {
        MBARRIER_EXPECT_TX(barb, STG2_B);
        TMA2D(tiles, &tmA2, kbase, bm, barb);
#pragma unroll
        for (int p = 0; p < 4; p++)
            TMA3D(tiles + 16384 + p * 8192, &tmB2, bn + p * 32, kbase, e, barb);
    }

    float c[4][4][4];
#pragma unroll
    for (int mi = 0; mi < 4; mi++)
#pragma unroll
        for (int ni = 0; ni < 4; ni++)
#pragma unroll
            for (int q = 0; q < 4; q++) c[mi][ni][q] = 0.0f;

    const int arow = wm * 64 + (lane & 15);
    const uint32_t alow = (uint32_t)((lane >> 4) * 16);
    uint32_t abasemi[4], axor[4];
#pragma unroll
    for (int mi = 0; mi < 4; mi++) {
        int r = arow + mi * 16;
        abasemi[mi] = (uint32_t)r << 7;
        axor[mi] = (uint32_t)(r & 7) << 4;
    }
    uint32_t bc0[4], bc1[4];
#pragma unroll
    for (int nj = 0; nj < 4; nj++) {
        uint32_t cb = (uint32_t)(nj * 8 + g) << 2;
        bc0[nj] = cb ^ ((uint32_t)(2 * tg) << 4);
        bc1[nj] = cb ^ ((uint32_t)(2 * tg + 1) << 4);
    }
    const uint32_t pb = tiles + 16384 + (uint32_t)wn * 8192;

    const int kt = (F_DIM / KSPLIT) / 64;   // 16

    for (int it = 0; it < kt; it++) {
        MBAR_WAIT(barb + (it & 1) * 8, (it >> 1) & 1);
        __syncthreads();

        if (tid == 0 && it + 1 < kt) {
            const uint32_t st = tiles + (uint32_t)((it + 1) & 1) * STG2_B;
            const uint32_t mb = barb + ((it + 1) & 1) * 8;
            const int k0 = kbase + (it + 1) * 64;
            MBARRIER_EXPECT_TX(mb, STG2_B);
            TMA2D(st, &tmA2, k0, bm, mb);
#pragma unroll
            for (int p = 0; p < 4; p++)
                TMA3D(st + 16384 + p * 8192, &tmB2, bn + p * 32, k0, e, mb);
        }

        const uint32_t soff = (uint32_t)(it & 1) * STG2_B;
        const uint32_t ab = tiles + soff;
#pragma unroll
        for (int ks = 0; ks < 4; ks++) {
            uint32_t a[4][4];
#pragma unroll
            for (int mi = 0; mi < 4; mi++) {
                uint32_t ad = ab + abasemi[mi]
                            + ((((uint32_t)ks << 5) | alow) ^ axor[mi]);
                ldsm4(a[mi][0], a[mi][1], a[mi][2], a[mi][3], ad);
            }
            const uint32_t rbyte = (uint32_t)(16 * ks + 2 * tg) << 7;
            const uint32_t rp = pb + soff + rbyte;
#pragma unroll
            for (int ni = 0; ni < 4; ni++) {
                float f0 = lds_f32(rp + bc0[ni]);
                float f1 = lds_f32(rp + 128 + bc1[ni]);
                float f2 = lds_f32(rp + 1024 + bc0[ni]);
                float f3 = lds_f32(rp + 1152 + bc1[ni]);
                uint32_t b0 = pack_h2(f0, f1);
                uint32_t b1 = pack_h2(f2, f3);
#pragma unroll
                for (int mi = 0; mi < 4; mi++)
                    mma_f16(c[mi][ni][0], c[mi][ni][1], c[mi][ni][2], c[mi][ni][3],
                            a[mi][0], a[mi][1], a[mi][2], a[mi][3], b0, b1);
            }
        }
    }

    float* Yp = g_Y + (size_t)z * ((size_t)ROWS_CAP * H_DIM);
    const int r_base = bm + wm * 64;
    const int c_base = bn + wn * 32;
#pragma unroll
    for (int mi = 0; mi < 4; mi++) {
        int r0 = r_base + mi * 16 + g;
        size_t o0 = (size_t)r0 * H_DIM;
        size_t o1 = (size_t)(r0 + 8) * H_DIM;
#pragma unroll
        for (int ni = 0; ni < 4; ni++) {
            int cl = c_base + ni * 8 + 2 * tg;
            *reinterpret_cast<float2*>(Yp + o0 + cl) = make_float2(c[mi][ni][0], c[mi][ni][1]);
            *reinterpret_cast<float2*>(Yp + o1 + cl) = make_float2(c[mi][ni][2], c[mi][ni][3]);
        }
    }
}

__global__ void combine_kernel(float* __restrict__ out) {
    int i = blockIdx.x * blockDim.x + threadIdx.x;
    int t = i >> 9;
    int h = (i & 511) << 2;
    size_t r0 = (size_t)g_pos[2 * t] * H_DIM + h;
    size_t r1 = (size_t)g_pos[2 * t + 1] * H_DIM + h;
    const size_t SL = (size_t)ROWS_CAP * H_DIM;
    float4 s0 = make_float4(0.f, 0.f, 0.f, 0.f);
    float4 s1 = make_float4(0.f, 0.f, 0.f, 0.f);
#pragma unroll
    for (int zz = 0; zz < KSPLIT; zz++) {
        float4 a = *reinterpret_cast<const float4*>(g_Y + zz * SL + r0);
        float4 b = *reinterpret_cast<const float4*>(g_Y + zz * SL + r1);
        s0.x += a.x; s0.y += a.y; s0.z += a.z; s0.w += a.w;
        s1.x += b.x; s1.y += b.y; s1.z += b.z; s1.w += b.w;
    }
    *reinterpret_cast<float4*>(out + (size_t)t * H_DIM + h) =
        make_float4(s0.x + s1.x, s0.y + s1.y, s0.z + s1.z, s0.w + s1.w);
}

// ------------------------------- host --------------------------------------
typedef CUresult (*encode_fn_t)(CUtensorMap*, CUtensorMapDataType, unsigned, void*,
                                const unsigned long long*, const unsigned long long*,
                                const unsigned*, const unsigned*, CUtensorMapInterleave,
                                CUtensorMapSwizzle, CUtensorMapL2promotion,
                                CUtensorMapFloatOOBfill);

extern "C" void kernel_launch(void* const* d_in, const int* in_sizes, int n_in,
                              void* d_out, int out_size) {
    const float* x  = (const float*)d_in[0];
    const float* wg = (const float*)d_in[1];
    const float* w1 = (const float*)d_in[2];
    const float* w3 = (const float*)d_in[3];
    const float* w2 = (const float*)d_in[4];
    float* out = (float*)d_out;

    void* encp = nullptr;
    cudaDriverEntryPointQueryResult qr;
    cudaGetDriverEntryPoint("cuTensorMapEncodeTiled", &encp, cudaEnableDefault, &qr);
    encode_fn_t enc = (encode_fn_t)encp;

    void* pX = nullptr; cudaGetSymbolAddress(&pX, g_X);
    void* pA = nullptr; cudaGetSymbolAddress(&pA, g_A);

    CUtensorMap tmA, tmA2;
    {
        unsigned long long dims[2] = {H_DIM, ROWS_CAP};
        unsigned long long strides[1] = {H_DIM * 2ull};
        unsigned box[2] = {64u, 128u};
        unsigned es[2] = {1u, 1u};
        enc(&tmA, CU_TENSOR_MAP_DATA_TYPE_FLOAT16, 2, pX, dims, strides, box, es,
            CU_TENSOR_MAP_INTERLEAVE_NONE, CU_TENSOR_MAP_SWIZZLE_128B,
            CU_TENSOR_MAP_L2_PROMOTION_L2_128B, CU_TENSOR_MAP_FLOAT_OOB_FILL_NONE);
        unsigned long long dims2[2] = {F_DIM, ROWS_CAP};
        unsigned long long strides2[1] = {F_DIM * 2ull};
        enc(&tmA2, CU_TENSOR_MAP_DATA_TYPE_FLOAT16, 2, pA, dims2, strides2, box, es,
            CU_TENSOR_MAP_INTERLEAVE_NONE, CU_TENSOR_MAP_SWIZZLE_128B,
            CU_TENSOR_MAP_L2_PROMOTION_L2_128B, CU_TENSOR_MAP_FLOAT_OOB_FILL_NONE);
    }
    CUtensorMap tmW1, tmW3, tmW2;
    {
        unsigned long long dims[3] = {F_DIM, H_DIM, E_EXP};
        unsigned long long strides[2] = {F_DIM * 4ull, (unsigned long long)F_DIM * H_DIM * 4ull};
        unsigned box[3] = {32u, 64u, 1u};
        unsigned es[3] = {1u, 1u, 1u};
        enc(&tmW1, CU_TENSOR_MAP_DATA_TYPE_FLOAT32, 3, (void*)w1, dims, strides, box, es,
            CU_TENSOR_MAP_INTERLEAVE_NONE, CU_TENSOR_MAP_SWIZZLE_128B,
            CU_TENSOR_MAP_L2_PROMOTION_L2_128B, CU_TENSOR_MAP_FLOAT_OOB_FILL_NONE);
        enc(&tmW3, CU_TENSOR_MAP_DATA_TYPE_FLOAT32, 3, (void*)w3, dims, strides, box, es,
            CU_TENSOR_MAP_INTERLEAVE_NONE, CU_TENSOR_MAP_SWIZZLE_128B,
            CU_TENSOR_MAP_L2_PROMOTION_L2_128B, CU_TENSOR_MAP_FLOAT_OOB_FILL_NONE);
        unsigned long long dims2[3] = {H_DIM, F_DIM, E_EXP};
        unsigned long long strides2[2] = {H_DIM * 4ull, (unsigned long long)H_DIM * F_DIM * 4ull};
        enc(&tmW2, CU_TENSOR_MAP_DATA_TYPE_FLOAT32, 3, (void*)w2, dims2, strides2, box, es,
            CU_TENSOR_MAP_INTERLEAVE_NONE, CU_TENSOR_MAP_SWIZZLE_128B,
            CU_TENSOR_MAP_L2_PROMOTION_L2_128B, CU_TENSOR_MAP_FLOAT_OOB_FILL_NONE);
    }

    cudaFuncSetAttribute(gemm13_kernel, cudaFuncAttributeMaxDynamicSharedMemorySize, SMEM13);
    cudaFuncSetAttribute(gemm2_kernel, cudaFuncAttributeMaxDynamicSharedMemorySize, SMEM2);

    gate_kernel<<<T_TOK / 8, 256>>>(x, wg);
    route_scatter_kernel<<<1, 256>>>();
    gather_kernel<<<ROWS_CAP * 512 / 256, 256>>>(x);

    dim3 g1(F_DIM / 64, MTILES);
    gemm13_kernel<<<g1, 256, SMEM13>>>(tmA, tmW1, tmW3);

    dim3 g2(H_DIM / 128, MTILES, KSPLIT);
    gemm2_kernel<<<g2, 256, SMEM2>>>(tmA2, tmW2);

    combine_kernel<<<(T_TOK * H_DIM / 4) / 256, 256>>>(out);
}